// round 2
// baseline (speedup 1.0000x reference)
#include <cuda_runtime.h>
#include <math.h>

#define BB 256
#define TT 256
#define II 512
#define HH 512

#define TM 32      // batch rows per block
#define TH 32      // h-columns per block
#define TN 128     // gate columns per block = 4 * TH
#define KT 32      // k-chunk
#define NTHR 256

// persistent scratch (allocation-free rule: __device__ globals)
__device__ float g_h[2][BB * HH];
__device__ float g_c[BB * HH];

__device__ __forceinline__ void ffma2(unsigned long long& d,
                                      unsigned long long a,
                                      unsigned long long b) {
    asm("fma.rn.f32x2 %0, %1, %2, %0;" : "+l"(d) : "l"(a), "l"(b));
}

__device__ __forceinline__ float2 ull_as_f2(unsigned long long v) {
    float2 r;
    asm("mov.b64 {%0, %1}, %2;" : "=f"(r.x), "=f"(r.y) : "l"(v));
    return r;
}

__device__ __forceinline__ float sigmoidf_(float x) {
    return 1.0f / (1.0f + expf(-x));
}

__global__ void lstm_init_kernel() {
    int i = blockIdx.x * blockDim.x + threadIdx.x;
    if (i < BB * HH) {
        g_h[0][i] = 0.0f;
        g_h[1][i] = 0.0f;
        g_c[i]    = 0.0f;
    }
}

// One timestep: g = [x_t | h] @ [W_ih | W_hh]^T + (b_ih+b_hh); gates; c,h update.
// Block tile: TM batches x TN gate-cols (4 gates x TH h-cols, so the
// elementwise update is block-local). K = I + H = 1024.
__global__ void __launch_bounds__(NTHR, 1) lstm_step_kernel(
    const float* __restrict__ x,     // [B,T,I]
    const float* __restrict__ W_ih,  // [4H, I]
    const float* __restrict__ W_hh,  // [4H, H]
    const float* __restrict__ b_ih,  // [4H]
    const float* __restrict__ b_hh,  // [4H]
    int t)
{
    __shared__ __align__(16) float2 As2[KT][TM + 1];   // A vals duplicated as pairs
    __shared__ __align__(16) float  Bs[KT][TN + 4];    // B tile (reused as g staging)

    const float* __restrict__ h_in = g_h[t & 1];
    float* __restrict__ h_out      = g_h[(t + 1) & 1];

    const int tid = threadIdx.x;
    const int b0  = blockIdx.x * TM;   // batch base
    const int j0  = blockIdx.y * TH;   // h-column base

    const int tm  = tid >> 5;          // 0..7  -> batch micro-rows tm*4..tm*4+3
    const int tn  = tid & 31;          // 0..31 -> gate micro-cols tn*4..tn*4+3
    const int tm4 = tm * 4;
    const int tn4 = tn * 4;

    unsigned long long acc[4][2];      // 4 batches x 2 f32x2 pairs (4 n-cols)
#pragma unroll
    for (int i = 0; i < 4; i++) { acc[i][0] = 0ull; acc[i][1] = 0ull; }

    // loader indices
    const int ar = tid >> 3;           // A: row 0..31
    const int ac = tid & 7;            // A: float4 col 0..7

    for (int kc = 0; kc < 32; kc++) {
        // ---- load A tile (TM x KT): k<512 from x[:,t,:], else from h_in ----
        {
            const int kb = kc * KT + ac * 4;
            float4 av;
            if (kc < 16) {
                av = *(const float4*)&x[((b0 + ar) * TT + t) * II + kb];
            } else {
                av = *(const float4*)&h_in[(b0 + ar) * HH + (kb - II)];
            }
            As2[ac * 4 + 0][ar] = make_float2(av.x, av.x);
            As2[ac * 4 + 1][ar] = make_float2(av.y, av.y);
            As2[ac * 4 + 2][ar] = make_float2(av.z, av.z);
            As2[ac * 4 + 3][ar] = make_float2(av.w, av.w);
        }
        // ---- load B tile (TN x KT): rows = 4 gates x TH cols of W ----
#pragma unroll
        for (int q = 0; q < 4; q++) {
            const int f  = tid + NTHR * q;   // 0..1023
            const int n  = f >> 3;           // 0..127
            const int cc = f & 7;
            const int gate = n >> 5;
            const int grow = (gate << 9) + j0 + (n & 31);
            float4 wv;
            if (kc < 16) {
                wv = *(const float4*)&W_ih[grow * II + kc * KT + cc * 4];
            } else {
                wv = *(const float4*)&W_hh[grow * HH + (kc - 16) * KT + cc * 4];
            }
            Bs[cc * 4 + 0][n] = wv.x;
            Bs[cc * 4 + 1][n] = wv.y;
            Bs[cc * 4 + 2][n] = wv.z;
            Bs[cc * 4 + 3][n] = wv.w;
        }
        __syncthreads();

        // ---- inner product: FFMA2 (packed fp32), 8 per thread per kk ----
#pragma unroll
        for (int kk = 0; kk < KT; kk++) {
            unsigned long long a0 = *(const unsigned long long*)&As2[kk][tm4 + 0];
            unsigned long long a1 = *(const unsigned long long*)&As2[kk][tm4 + 1];
            unsigned long long a2 = *(const unsigned long long*)&As2[kk][tm4 + 2];
            unsigned long long a3 = *(const unsigned long long*)&As2[kk][tm4 + 3];
            ulonglong2 bb = *(const ulonglong2*)&Bs[kk][tn4];
            ffma2(acc[0][0], a0, bb.x); ffma2(acc[0][1], a0, bb.y);
            ffma2(acc[1][0], a1, bb.x); ffma2(acc[1][1], a1, bb.y);
            ffma2(acc[2][0], a2, bb.x); ffma2(acc[2][1], a2, bb.y);
            ffma2(acc[3][0], a3, bb.x); ffma2(acc[3][1], a3, bb.y);
        }
        __syncthreads();
    }

    // ---- unpack + bias ----
    float gv[4][4];
#pragma unroll
    for (int i = 0; i < 4; i++) {
        float2 v0 = ull_as_f2(acc[i][0]);
        float2 v1 = ull_as_f2(acc[i][1]);
        gv[i][0] = v0.x; gv[i][1] = v0.y; gv[i][2] = v1.x; gv[i][3] = v1.y;
    }
#pragma unroll
    for (int j = 0; j < 4; j++) {
        const int n_local = tn4 + j;
        const int grow = ((n_local >> 5) << 9) + j0 + (n_local & 31);
        const float bias = b_ih[grow] + b_hh[grow];
#pragma unroll
        for (int i = 0; i < 4; i++) gv[i][j] += bias;
    }

    // ---- stage g into smem (reuse Bs) so gates for same (b,j) are together ----
#pragma unroll
    for (int i = 0; i < 4; i++)
#pragma unroll
        for (int j = 0; j < 4; j++)
            Bs[tm4 + i][tn4 + j] = gv[i][j];
    __syncthreads();

    // ---- elementwise LSTM update: 32 batches x 32 h-cols, 4 per thread ----
#pragma unroll
    for (int u = 0; u < 4; u++) {
        const int idx = tid + NTHR * u;     // 0..1023
        const int bl  = idx >> 5;           // 0..31
        const int jl  = idx & 31;           // 0..31
        const float iv = sigmoidf_(Bs[bl][jl]);
        const float fv = sigmoidf_(Bs[bl][32 + jl]);
        const float gg = tanhf    (Bs[bl][64 + jl]);
        const float ov = sigmoidf_(Bs[bl][96 + jl]);
        const int gi = (b0 + bl) * HH + j0 + jl;
        const float cn = fv * g_c[gi] + iv * gg;
        g_c[gi]   = cn;
        h_out[gi] = ov * tanhf(cn);
    }
}

// out[b] = dot(h_last[b,:], fc_w[0,:]) + fc_b[0]
__global__ void lstm_final_kernel(const float* __restrict__ fc_w,
                                  const float* __restrict__ fc_b,
                                  float* __restrict__ out)
{
    const int b   = blockIdx.x;
    const int tid = threadIdx.x;   // 128 threads
    const float* h_last = g_h[TT & 1];   // T even -> buffer 0

    const float4 hv = *(const float4*)&h_last[b * HH + tid * 4];
    const float4 wv = *(const float4*)&fc_w[tid * 4];
    float s = hv.x * wv.x + hv.y * wv.y + hv.z * wv.z + hv.w * wv.w;

#pragma unroll
    for (int o = 16; o > 0; o >>= 1) s += __shfl_down_sync(0xFFFFFFFFu, s, o);

    __shared__ float ws[4];
    if ((tid & 31) == 0) ws[tid >> 5] = s;
    __syncthreads();
    if (tid == 0) out[b] = ws[0] + ws[1] + ws[2] + ws[3] + fc_b[0];
}

extern "C" void kernel_launch(void* const* d_in, const int* in_sizes, int n_in,
                              void* d_out, int out_size)
{
    const float* x    = (const float*)d_in[0];
    const float* W_ih = (const float*)d_in[1];
    const float* W_hh = (const float*)d_in[2];
    const float* b_ih = (const float*)d_in[3];
    const float* b_hh = (const float*)d_in[4];
    const float* fc_w = (const float*)d_in[5];
    const float* fc_b = (const float*)d_in[6];
    float* out = (float*)d_out;

    lstm_init_kernel<<<(BB * HH + 255) / 256, 256>>>();

    dim3 grid(BB / TM, HH / TH);   // 8 x 16 = 128 blocks
    for (int t = 0; t < TT; t++) {
        lstm_step_kernel<<<grid, NTHR>>>(x, W_ih, W_hh, b_ih, b_hh, t);
    }

    lstm_final_kernel<<<BB, 128>>>(fc_w, fc_b, out);
}

// round 3
// speedup vs baseline: 1.0007x; 1.0007x over previous
#include <cuda_runtime.h>
#include <math.h>

#define BB 256
#define TT 256
#define II 512
#define HH 512

#define TM 32      // batch rows per block
#define TH 32      // h-columns per block
#define TN 128     // gate columns per block = 4 * TH
#define KT 32      // k-chunk
#define NTHR 256

// persistent scratch (allocation-free rule: __device__ globals)
__device__ float g_h[2][BB * HH];
__device__ float g_c[BB * HH];

__device__ __forceinline__ void ffma2(unsigned long long& d,
                                      unsigned long long a,
                                      unsigned long long b) {
    asm("fma.rn.f32x2 %0, %1, %2, %0;" : "+l"(d) : "l"(a), "l"(b));
}

__device__ __forceinline__ float2 ull_as_f2(unsigned long long v) {
    float2 r;
    asm("mov.b64 {%0, %1}, %2;" : "=f"(r.x), "=f"(r.y) : "l"(v));
    return r;
}

__device__ __forceinline__ float sigmoidf_(float x) {
    return 1.0f / (1.0f + expf(-x));
}

__global__ void lstm_init_kernel() {
    int i = blockIdx.x * blockDim.x + threadIdx.x;
    if (i < BB * HH) {
        g_h[0][i] = 0.0f;
        g_h[1][i] = 0.0f;
        g_c[i]    = 0.0f;
    }
}

// One timestep: g = [x_t | h] @ [W_ih | W_hh]^T + (b_ih+b_hh); gates; c,h update.
// Block tile: TM batches x TN gate-cols (4 gates x TH h-cols, so the
// elementwise update is block-local). K = I + H = 1024.
__global__ void __launch_bounds__(NTHR, 1) lstm_step_kernel(
    const float* __restrict__ x,     // [B,T,I]
    const float* __restrict__ W_ih,  // [4H, I]
    const float* __restrict__ W_hh,  // [4H, H]
    const float* __restrict__ b_ih,  // [4H]
    const float* __restrict__ b_hh,  // [4H]
    int t)
{
    __shared__ __align__(16) float2 As2[KT][TM + 1];   // A vals duplicated as pairs
    __shared__ __align__(16) float  Bs[KT][TN + 4];    // B tile (reused as g staging)

    const float* __restrict__ h_in = g_h[t & 1];
    float* __restrict__ h_out      = g_h[(t + 1) & 1];

    const int tid = threadIdx.x;
    const int b0  = blockIdx.x * TM;   // batch base
    const int j0  = blockIdx.y * TH;   // h-column base

    const int tm  = tid >> 5;          // 0..7  -> batch micro-rows tm*4..tm*4+3
    const int tn  = tid & 31;          // 0..31 -> gate micro-cols tn*4..tn*4+3
    const int tm4 = tm * 4;
    const int tn4 = tn * 4;

    unsigned long long acc[4][2];      // 4 batches x 2 f32x2 pairs (4 n-cols)
#pragma unroll
    for (int i = 0; i < 4; i++) { acc[i][0] = 0ull; acc[i][1] = 0ull; }

    // loader indices
    const int ar = tid >> 3;           // A: row 0..31
    const int ac = tid & 7;            // A: float4 col 0..7

    for (int kc = 0; kc < 32; kc++) {
        // ---- load A tile (TM x KT): k<512 from x[:,t,:], else from h_in ----
        {
            const int kb = kc * KT + ac * 4;
            float4 av;
            if (kc < 16) {
                av = *(const float4*)&x[((b0 + ar) * TT + t) * II + kb];
            } else {
                av = *(const float4*)&h_in[(b0 + ar) * HH + (kb - II)];
            }
            As2[ac * 4 + 0][ar] = make_float2(av.x, av.x);
            As2[ac * 4 + 1][ar] = make_float2(av.y, av.y);
            As2[ac * 4 + 2][ar] = make_float2(av.z, av.z);
            As2[ac * 4 + 3][ar] = make_float2(av.w, av.w);
        }
        // ---- load B tile (TN x KT): rows = 4 gates x TH cols of W ----
#pragma unroll
        for (int q = 0; q < 4; q++) {
            const int f  = tid + NTHR * q;   // 0..1023
            const int n  = f >> 3;           // 0..127
            const int cc = f & 7;
            const int gate = n >> 5;
            const int grow = (gate << 9) + j0 + (n & 31);
            float4 wv;
            if (kc < 16) {
                wv = *(const float4*)&W_ih[grow * II + kc * KT + cc * 4];
            } else {
                wv = *(const float4*)&W_hh[grow * HH + (kc - 16) * KT + cc * 4];
            }
            Bs[cc * 4 + 0][n] = wv.x;
            Bs[cc * 4 + 1][n] = wv.y;
            Bs[cc * 4 + 2][n] = wv.z;
            Bs[cc * 4 + 3][n] = wv.w;
        }
        __syncthreads();

        // ---- inner product: FFMA2 (packed fp32), 8 per thread per kk ----
#pragma unroll
        for (int kk = 0; kk < KT; kk++) {
            unsigned long long a0 = *(const unsigned long long*)&As2[kk][tm4 + 0];
            unsigned long long a1 = *(const unsigned long long*)&As2[kk][tm4 + 1];
            unsigned long long a2 = *(const unsigned long long*)&As2[kk][tm4 + 2];
            unsigned long long a3 = *(const unsigned long long*)&As2[kk][tm4 + 3];
            ulonglong2 bb = *(const ulonglong2*)&Bs[kk][tn4];
            ffma2(acc[0][0], a0, bb.x); ffma2(acc[0][1], a0, bb.y);
            ffma2(acc[1][0], a1, bb.x); ffma2(acc[1][1], a1, bb.y);
            ffma2(acc[2][0], a2, bb.x); ffma2(acc[2][1], a2, bb.y);
            ffma2(acc[3][0], a3, bb.x); ffma2(acc[3][1], a3, bb.y);
        }
        __syncthreads();
    }

    // ---- unpack + bias ----
    float gv[4][4];
#pragma unroll
    for (int i = 0; i < 4; i++) {
        float2 v0 = ull_as_f2(acc[i][0]);
        float2 v1 = ull_as_f2(acc[i][1]);
        gv[i][0] = v0.x; gv[i][1] = v0.y; gv[i][2] = v1.x; gv[i][3] = v1.y;
    }
#pragma unroll
    for (int j = 0; j < 4; j++) {
        const int n_local = tn4 + j;
        const int grow = ((n_local >> 5) << 9) + j0 + (n_local & 31);
        const float bias = b_ih[grow] + b_hh[grow];
#pragma unroll
        for (int i = 0; i < 4; i++) gv[i][j] += bias;
    }

    // ---- stage g into smem (reuse Bs) so gates for same (b,j) are together ----
#pragma unroll
    for (int i = 0; i < 4; i++)
#pragma unroll
        for (int j = 0; j < 4; j++)
            Bs[tm4 + i][tn4 + j] = gv[i][j];
    __syncthreads();

    // ---- elementwise LSTM update: 32 batches x 32 h-cols, 4 per thread ----
#pragma unroll
    for (int u = 0; u < 4; u++) {
        const int idx = tid + NTHR * u;     // 0..1023
        const int bl  = idx >> 5;           // 0..31
        const int jl  = idx & 31;           // 0..31
        const float iv = sigmoidf_(Bs[bl][jl]);
        const float fv = sigmoidf_(Bs[bl][32 + jl]);
        const float gg = tanhf    (Bs[bl][64 + jl]);
        const float ov = sigmoidf_(Bs[bl][96 + jl]);
        const int gi = (b0 + bl) * HH + j0 + jl;
        const float cn = fv * g_c[gi] + iv * gg;
        g_c[gi]   = cn;
        h_out[gi] = ov * tanhf(cn);
    }
}

// out[b] = dot(h_last[b,:], fc_w[0,:]) + fc_b[0]
__global__ void lstm_final_kernel(const float* __restrict__ fc_w,
                                  const float* __restrict__ fc_b,
                                  float* __restrict__ out)
{
    const int b   = blockIdx.x;
    const int tid = threadIdx.x;   // 128 threads
    const float* h_last = g_h[TT & 1];   // T even -> buffer 0

    const float4 hv = *(const float4*)&h_last[b * HH + tid * 4];
    const float4 wv = *(const float4*)&fc_w[tid * 4];
    float s = hv.x * wv.x + hv.y * wv.y + hv.z * wv.z + hv.w * wv.w;

#pragma unroll
    for (int o = 16; o > 0; o >>= 1) s += __shfl_down_sync(0xFFFFFFFFu, s, o);

    __shared__ float ws[4];
    if ((tid & 31) == 0) ws[tid >> 5] = s;
    __syncthreads();
    if (tid == 0) out[b] = ws[0] + ws[1] + ws[2] + ws[3] + fc_b[0];
}

extern "C" void kernel_launch(void* const* d_in, const int* in_sizes, int n_in,
                              void* d_out, int out_size)
{
    const float* x    = (const float*)d_in[0];
    const float* W_ih = (const float*)d_in[1];
    const float* W_hh = (const float*)d_in[2];
    const float* b_ih = (const float*)d_in[3];
    const float* b_hh = (const float*)d_in[4];
    const float* fc_w = (const float*)d_in[5];
    const float* fc_b = (const float*)d_in[6];
    float* out = (float*)d_out;

    lstm_init_kernel<<<(BB * HH + 255) / 256, 256>>>();

    dim3 grid(BB / TM, HH / TH);   // 8 x 16 = 128 blocks
    for (int t = 0; t < TT; t++) {
        lstm_step_kernel<<<grid, NTHR>>>(x, W_ih, W_hh, b_ih, b_hh, t);
    }

    lstm_final_kernel<<<BB, 128>>>(fc_w, fc_b, out);
}